// round 6
// baseline (speedup 1.0000x reference)
#include <cuda_runtime.h>
#include <cstdint>

#define NHEAD 12
#define NB    64
#define NTOK  577
#define NC    768
#define ND    64
#define NKEEP 289          // tokens kept incl. CLS
#define NMASK 576
#define MROWS (NB*NTOK)    // 36928
#define QCOLS (3*NC)       // 2304
#define NPAD  296          // padded kept-token count (37 x 8)
#define NT8   37           // n-tiles of 8 in padded token dim

// ---------------- scratch (static device globals; no allocations) -------------
__device__ __align__(16) float g_q [(size_t)NB*NHEAD*NTOK*ND];   // [B,H,N,D]
__device__ __align__(16) float g_kp[(size_t)NB*NHEAD*NKEEP*ND];  // gathered K
__device__ __align__(16) float g_vp[(size_t)NB*NHEAD*NKEEP*ND];  // gathered V
__device__ __align__(16) float g_ao[(size_t)NB*NTOK*NC];         // attn out [B,N,C]
__device__ int g_dest[NB*NHEAD*NTOK];                            // token -> kept slot (-1 = dropped)

// ---------------- helpers ------------------------------------------------------
__device__ __forceinline__ float tf32_rna(float v) {
    uint32_t u;
    asm("cvt.rna.tf32.f32 %0, %1;" : "=r"(u) : "f"(v));
    return __uint_as_float(u);
}
__device__ __forceinline__ void mma_tf32(float* c, const uint32_t* a, const uint32_t* b) {
    asm volatile(
        "mma.sync.aligned.m16n8k8.row.col.f32.tf32.tf32.f32 "
        "{%0,%1,%2,%3}, {%4,%5,%6,%7}, {%8,%9}, {%0,%1,%2,%3};\n"
        : "+f"(c[0]), "+f"(c[1]), "+f"(c[2]), "+f"(c[3])
        : "r"(a[0]), "r"(a[1]), "r"(a[2]), "r"(a[3]), "r"(b[0]), "r"(b[1]));
}

// ---------------- token selection: exact top-288 of 576 per (b,h) -------------
__global__ __launch_bounds__(256) void select_kernel(const float* __restrict__ mask)
{
    int row = blockIdx.x;                       // b*NHEAD + h
    __shared__ float v[NMASK];
    __shared__ unsigned char keep[NMASK];
    const float* mrow = mask + (size_t)row * NMASK;
    for (int i = threadIdx.x; i < NMASK; i += 256) v[i] = mrow[i];
    __syncthreads();
    for (int i = threadIdx.x; i < NMASK; i += 256) {
        float vi = v[i];
        int cnt = 0;
        for (int j = 0; j < NMASK; ++j) {
            float vj = v[j];
            cnt += (vj > vi) || (vj == vi && j < i);   // top_k tie-break: lower index wins
        }
        keep[i] = (cnt < (NKEEP - 1)) ? 1 : 0;
    }
    __syncthreads();
    if (threadIdx.x == 0) {
        int* dm = g_dest + (size_t)row * NTOK;
        dm[0] = 0;
        int pos = 0;
        for (int i = 0; i < NMASK; ++i)
            dm[1 + i] = keep[i] ? (++pos) : -1;
    }
}

// ---------------- 128x128x16 tf32 mma.sync GEMM (unchanged from R5) -----------
template<int LDW, bool SCATTER, bool USE_AO>
__global__ __launch_bounds__(256, 2) void gemm_mma(const float* __restrict__ Ain,
                                                   const float* __restrict__ W,
                                                   const float* __restrict__ bias,
                                                   float* __restrict__ out)
{
    const float* __restrict__ A = USE_AO ? (const float*)g_ao : Ain;
    __shared__ float As[2][16][132];   // [stage][k][m], padded
    __shared__ float Bs[2][16][132];   // [stage][k][n], padded
    const int K = NC;

    int tid  = threadIdx.x;
    int brow = blockIdx.y * 128;
    int bcol = blockIdx.x * 128;

    int ar0 = tid >> 2;
    int ac  = (tid & 3) << 2;
    int br0 = tid >> 5;
    int bc  = (tid & 31) << 2;

    int wid  = tid >> 5;
    int lane = tid & 31;
    int gid  = lane >> 2;
    int tid4 = lane & 3;
    int m0 = (wid >> 2) * 64;
    int n0 = (wid & 3) * 32;

    bool aok0 = (brow + ar0)      < MROWS;
    bool aok1 = (brow + ar0 + 64) < MROWS;
    const float* Ap0 = A + (size_t)(brow + ar0) * K + ac;
    const float* Ap1 = Ap0 + (size_t)64 * K;
    const float* Wp  = W + (size_t)br0 * LDW + bcol + bc;

    const float4 z4 = make_float4(0.f, 0.f, 0.f, 0.f);
    float4 pa0 = aok0 ? *(const float4*)Ap0 : z4;
    float4 pa1 = aok1 ? *(const float4*)Ap1 : z4;
    float4 pb0 = *(const float4*)Wp;
    float4 pb1 = *(const float4*)(Wp + (size_t)8 * LDW);

    As[0][ac+0][ar0] = tf32_rna(pa0.x); As[0][ac+1][ar0] = tf32_rna(pa0.y);
    As[0][ac+2][ar0] = tf32_rna(pa0.z); As[0][ac+3][ar0] = tf32_rna(pa0.w);
    As[0][ac+0][ar0+64] = tf32_rna(pa1.x); As[0][ac+1][ar0+64] = tf32_rna(pa1.y);
    As[0][ac+2][ar0+64] = tf32_rna(pa1.z); As[0][ac+3][ar0+64] = tf32_rna(pa1.w);
    Bs[0][br0][bc+0]   = tf32_rna(pb0.x); Bs[0][br0][bc+1]   = tf32_rna(pb0.y);
    Bs[0][br0][bc+2]   = tf32_rna(pb0.z); Bs[0][br0][bc+3]   = tf32_rna(pb0.w);
    Bs[0][br0+8][bc+0] = tf32_rna(pb1.x); Bs[0][br0+8][bc+1] = tf32_rna(pb1.y);
    Bs[0][br0+8][bc+2] = tf32_rna(pb1.z); Bs[0][br0+8][bc+3] = tf32_rna(pb1.w);
    __syncthreads();

    float c[4][4][4];
    #pragma unroll
    for (int mt = 0; mt < 4; ++mt)
        #pragma unroll
        for (int nt = 0; nt < 4; ++nt)
            #pragma unroll
            for (int r = 0; r < 4; ++r) c[mt][nt][r] = 0.f;

    int buf = 0;
    for (int kt = 16; kt <= K; kt += 16) {
        bool more = kt < K;
        if (more) {
            pa0 = aok0 ? *(const float4*)(Ap0 + kt) : z4;
            pa1 = aok1 ? *(const float4*)(Ap1 + kt) : z4;
            pb0 = *(const float4*)(Wp + (size_t)kt * LDW);
            pb1 = *(const float4*)(Wp + (size_t)(kt + 8) * LDW);
        }
        #pragma unroll
        for (int ks = 0; ks < 2; ++ks) {
            const int kb = ks * 8;
            uint32_t bf[4][2], af[4][4];
            #pragma unroll
            for (int nt = 0; nt < 4; ++nt) {
                bf[nt][0] = __float_as_uint(Bs[buf][kb + tid4][n0 + nt*8 + gid]);
                bf[nt][1] = __float_as_uint(Bs[buf][kb + tid4 + 4][n0 + nt*8 + gid]);
            }
            #pragma unroll
            for (int mt = 0; mt < 4; ++mt) {
                af[mt][0] = __float_as_uint(As[buf][kb + tid4][m0 + mt*16 + gid]);
                af[mt][1] = __float_as_uint(As[buf][kb + tid4][m0 + mt*16 + gid + 8]);
                af[mt][2] = __float_as_uint(As[buf][kb + tid4 + 4][m0 + mt*16 + gid]);
                af[mt][3] = __float_as_uint(As[buf][kb + tid4 + 4][m0 + mt*16 + gid + 8]);
            }
            #pragma unroll
            for (int mt = 0; mt < 4; ++mt)
                #pragma unroll
                for (int nt = 0; nt < 4; ++nt)
                    mma_tf32(c[mt][nt], af[mt], bf[nt]);
        }
        if (more) {
            int nb = buf ^ 1;
            As[nb][ac+0][ar0] = tf32_rna(pa0.x); As[nb][ac+1][ar0] = tf32_rna(pa0.y);
            As[nb][ac+2][ar0] = tf32_rna(pa0.z); As[nb][ac+3][ar0] = tf32_rna(pa0.w);
            As[nb][ac+0][ar0+64] = tf32_rna(pa1.x); As[nb][ac+1][ar0+64] = tf32_rna(pa1.y);
            As[nb][ac+2][ar0+64] = tf32_rna(pa1.z); As[nb][ac+3][ar0+64] = tf32_rna(pa1.w);
            Bs[nb][br0][bc+0]   = tf32_rna(pb0.x); Bs[nb][br0][bc+1]   = tf32_rna(pb0.y);
            Bs[nb][br0][bc+2]   = tf32_rna(pb0.z); Bs[nb][br0][bc+3]   = tf32_rna(pb0.w);
            Bs[nb][br0+8][bc+0] = tf32_rna(pb1.x); Bs[nb][br0+8][bc+1] = tf32_rna(pb1.y);
            Bs[nb][br0+8][bc+2] = tf32_rna(pb1.z); Bs[nb][br0+8][bc+3] = tf32_rna(pb1.w);
            __syncthreads();
            buf = nb;
        }
    }

    int colbase = bcol + n0;
    int s  = colbase / NC;
    int hd = colbase - s * NC;
    int h  = hd >> 6;

    #pragma unroll
    for (int mt = 0; mt < 4; ++mt) {
        #pragma unroll
        for (int half = 0; half < 2; ++half) {
            int m = brow + m0 + mt * 16 + gid + half * 8;
            if (m >= MROWS) continue;
            float* dst = nullptr;
            int d_off = 0;
            if (SCATTER) {
                int b  = m / NTOK;
                int n  = m - b * NTOK;
                int bh = b * NHEAD + h;
                if (s == 0) {
                    dst = &g_q[((size_t)bh * NTOK + n) * ND];
                } else {
                    int dest = g_dest[bh * NTOK + n];
                    if (dest >= 0)
                        dst = &((s == 1) ? g_kp : g_vp)[((size_t)bh * NKEEP + dest) * ND];
                }
                d_off = hd & 63;
            } else {
                dst = out + (size_t)m * LDW + colbase;
            }
            if (!dst) continue;
            #pragma unroll
            for (int nt = 0; nt < 4; ++nt) {
                int cl = nt * 8 + tid4 * 2;
                float2 bv = *(const float2*)(bias + colbase + cl);
                float2 o;
                o.x = c[mt][nt][half * 2 + 0] + bv.x;
                o.y = c[mt][nt][half * 2 + 1] + bv.y;
                *(float2*)(dst + (SCATTER ? d_off : 0) + cl) = o;
            }
        }
    }
}

// ---------------- attention with tf32 mma.sync ---------------------------------
// CTA: (b,h) x 32-query tile. Strides chosen for conflict-free fragment LDS:
//   Qs/Ks stride 68 (=4 mod 32), Vs stride 72 (t4*8+g distinct), Ss stride 300.
#define QS_STR 68
#define KS_STR 68
#define VS_STR 72
#define SS_STR 300
#define ATTN_SMEM ((32*QS_STR + NPAD*KS_STR + NPAD*VS_STR + 32*SS_STR) * 4)

__global__ __launch_bounds__(256) void attn_mma()
{
    extern __shared__ float sh[];
    float* Qs = sh;                        // 32 x 68
    float* Ks = Qs + 32 * QS_STR;          // 296 x 68
    float* Vs = Ks + NPAD * KS_STR;        // 296 x 72
    float* Ss = Vs + NPAD * VS_STR;        // 32 x 300

    int tid  = threadIdx.x;
    int bh   = blockIdx.y;
    int q0   = blockIdx.x * 32;
    int wid  = tid >> 5;
    int lane = tid & 31;
    int gid  = lane >> 2;
    int t4   = lane & 3;

    // ---- load K/V (tf32-rounded, pad rows zeroed) and Q tile ----
    const float* kp = g_kp + (size_t)bh * NKEEP * ND;
    const float* vp = g_vp + (size_t)bh * NKEEP * ND;
    for (int idx = tid; idx < NPAD * ND; idx += 256) {
        int m = idx >> 6, d = idx & 63;
        float kv = 0.f, vv = 0.f;
        if (m < NKEEP) {
            kv = tf32_rna(kp[(size_t)m * ND + d]);
            vv = tf32_rna(vp[(size_t)m * ND + d]);
        }
        Ks[m * KS_STR + d] = kv;
        Vs[m * VS_STR + d] = vv;
    }
    const float* qp = g_q + (size_t)bh * NTOK * ND;
    for (int idx = tid; idx < 32 * ND; idx += 256) {
        int qq = idx >> 6, d = idx & 63;
        int qg = q0 + qq;
        Qs[qq * QS_STR + d] = (qg < NTOK) ? tf32_rna(qp[(size_t)qg * ND + d]) : 0.f;
    }
    __syncthreads();

    // ---- Phase A: S = (Q K^T) * scale via mma ----
    {
        int wm = wid & 1, wn = wid >> 1;
        int m0 = wm * 16;
        for (int nt = wn; nt < NT8; nt += 4) {
            int nb = nt * 8;
            float c[4] = {0.f, 0.f, 0.f, 0.f};
            #pragma unroll
            for (int ks = 0; ks < 8; ++ks) {
                int k0 = ks * 8;
                uint32_t a[4], b[2];
                a[0] = __float_as_uint(Qs[(m0 + gid) * QS_STR + k0 + t4]);
                a[1] = __float_as_uint(Qs[(m0 + gid + 8) * QS_STR + k0 + t4]);
                a[2] = __float_as_uint(Qs[(m0 + gid) * QS_STR + k0 + t4 + 4]);
                a[3] = __float_as_uint(Qs[(m0 + gid + 8) * QS_STR + k0 + t4 + 4]);
                b[0] = __float_as_uint(Ks[(nb + gid) * KS_STR + k0 + t4]);
                b[1] = __float_as_uint(Ks[(nb + gid) * KS_STR + k0 + t4 + 4]);
                mma_tf32(c, a, b);
            }
            *(float2*)&Ss[(m0 + gid) * SS_STR + nb + 2 * t4]
                = make_float2(c[0] * 0.125f, c[1] * 0.125f);
            *(float2*)&Ss[(m0 + gid + 8) * SS_STR + nb + 2 * t4]
                = make_float2(c[2] * 0.125f, c[3] * 0.125f);
        }
    }
    __syncthreads();

    // ---- Phase B: row softmax over first NKEEP cols (pad cols stay 0) ----
    {
        int w = tid >> 5, ln = tid & 31;
        #pragma unroll
        for (int r = 0; r < 4; ++r) {
            float* Sr = Ss + (w * 4 + r) * SS_STR;
            float mx = -3.0e38f;
            for (int m = ln; m < NKEEP; m += 32) mx = fmaxf(mx, Sr[m]);
            #pragma unroll
            for (int o = 16; o; o >>= 1) mx = fmaxf(mx, __shfl_xor_sync(0xffffffffu, mx, o));
            float sum = 0.f;
            for (int m = ln; m < NKEEP; m += 32) {
                float e = __expf(Sr[m] - mx);
                Sr[m] = e;
                sum += e;
            }
            #pragma unroll
            for (int o = 16; o; o >>= 1) sum += __shfl_xor_sync(0xffffffffu, sum, o);
            float inv = 1.f / sum;
            for (int m = ln; m < NKEEP; m += 32) Sr[m] *= inv;
        }
    }
    __syncthreads();

    // ---- Phase C: O = P @ V via mma (K dim = 296, P pad cols are 0) ----
    {
        int wm = wid & 1, wn = wid >> 1;
        int m0 = wm * 16, n0 = wn * 16;
        float c[2][4];
        #pragma unroll
        for (int nt = 0; nt < 2; ++nt)
            #pragma unroll
            for (int r = 0; r < 4; ++r) c[nt][r] = 0.f;

        for (int ks = 0; ks < NT8; ++ks) {
            int k0 = ks * 8;
            uint32_t a[4];
            a[0] = __float_as_uint(tf32_rna(Ss[(m0 + gid) * SS_STR + k0 + t4]));
            a[1] = __float_as_uint(tf32_rna(Ss[(m0 + gid + 8) * SS_STR + k0 + t4]));
            a[2] = __float_as_uint(tf32_rna(Ss[(m0 + gid) * SS_STR + k0 + t4 + 4]));
            a[3] = __float_as_uint(tf32_rna(Ss[(m0 + gid + 8) * SS_STR + k0 + t4 + 4]));
            #pragma unroll
            for (int nt = 0; nt < 2; ++nt) {
                uint32_t b[2];
                b[0] = __float_as_uint(Vs[(k0 + t4) * VS_STR + n0 + nt * 8 + gid]);
                b[1] = __float_as_uint(Vs[(k0 + t4 + 4) * VS_STR + n0 + nt * 8 + gid]);
                mma_tf32(c[nt], a, b);
            }
        }

        int b = bh / NHEAD, h = bh - b * NHEAD;
        #pragma unroll
        for (int half = 0; half < 2; ++half) {
            int qg = q0 + m0 + gid + half * 8;
            if (qg >= NTOK) continue;
            float* dst = &g_ao[((size_t)(b * NTOK + qg)) * NC + h * ND + n0];
            #pragma unroll
            for (int nt = 0; nt < 2; ++nt) {
                float2 o;
                o.x = c[nt][half * 2 + 0];
                o.y = c[nt][half * 2 + 1];
                *(float2*)(dst + nt * 8 + 2 * t4) = o;
            }
        }
    }
}

// ---------------- launch -------------------------------------------------------
extern "C" void kernel_launch(void* const* d_in, const int* in_sizes, int n_in,
                              void* d_out, int out_size)
{
    const float* x     = (const float*)d_in[0];
    const float* mask  = (const float*)d_in[1];
    const float* Wqkv  = (const float*)d_in[2];
    const float* bqkv  = (const float*)d_in[3];
    const float* Wproj = (const float*)d_in[4];
    const float* bproj = (const float*)d_in[5];
    float* out = (float*)d_out;

    select_kernel<<<NB * NHEAD, 256>>>(mask);

    dim3 g1(QCOLS / 128, (MROWS + 127) / 128);
    gemm_mma<QCOLS, true, false><<<g1, 256>>>(x, Wqkv, bqkv, nullptr);

    cudaFuncSetAttribute(attn_mma, cudaFuncAttributeMaxDynamicSharedMemorySize, ATTN_SMEM);
    attn_mma<<<dim3((NTOK + 31) / 32, NB * NHEAD), 256, ATTN_SMEM>>>();

    dim3 g2(NC / 128, (MROWS + 127) / 128);
    gemm_mma<NC, false, true><<<g2, 256>>>(nullptr, Wproj, bproj, out);
}

// round 7
// speedup vs baseline: 1.5491x; 1.5491x over previous
#include <cuda_runtime.h>
#include <cstdint>

#define NHEAD 12
#define NB    64
#define NTOK  577
#define NC    768
#define ND    64
#define NKEEP 289          // tokens kept incl. CLS
#define NMASK 576
#define MROWS (NB*NTOK)    // 36928
#define QCOLS (3*NC)       // 2304
#define NPAD  296          // padded kept-token count (37 x 8)
#define NT8   37           // n-tiles of 8 in padded token dim

// ---------------- scratch (static device globals; no allocations) -------------
__device__ __align__(16) float g_q [(size_t)NB*NHEAD*NTOK*ND];   // [B,H,N,D]
__device__ __align__(16) float g_kp[(size_t)NB*NHEAD*NKEEP*ND];  // gathered K
__device__ __align__(16) float g_vp[(size_t)NB*NHEAD*NKEEP*ND];  // gathered V
__device__ __align__(16) float g_ao[(size_t)NB*NTOK*NC];         // attn out [B,N,C]
__device__ int g_dest[NB*NHEAD*NTOK];                            // token -> kept slot (-1 = dropped)

// ---------------- helpers ------------------------------------------------------
__device__ __forceinline__ float tf32_rna(float v) {
    uint32_t u;
    asm("cvt.rna.tf32.f32 %0, %1;" : "=r"(u) : "f"(v));
    return __uint_as_float(u);
}
__device__ __forceinline__ void mma_tf32(float* c, const uint32_t* a, const uint32_t* b) {
    asm volatile(
        "mma.sync.aligned.m16n8k8.row.col.f32.tf32.tf32.f32 "
        "{%0,%1,%2,%3}, {%4,%5,%6,%7}, {%8,%9}, {%0,%1,%2,%3};\n"
        : "+f"(c[0]), "+f"(c[1]), "+f"(c[2]), "+f"(c[3])
        : "r"(a[0]), "r"(a[1]), "r"(a[2]), "r"(a[3]), "r"(b[0]), "r"(b[1]));
}

// ---------------- token selection: exact top-288 of 576 per (b,h) -------------
__global__ __launch_bounds__(256) void select_kernel(const float* __restrict__ mask)
{
    int row = blockIdx.x;                       // b*NHEAD + h
    __shared__ float v[NMASK];
    __shared__ unsigned char keep[NMASK];
    const float* mrow = mask + (size_t)row * NMASK;
    for (int i = threadIdx.x; i < NMASK; i += 256) v[i] = mrow[i];
    __syncthreads();
    for (int i = threadIdx.x; i < NMASK; i += 256) {
        float vi = v[i];
        int cnt = 0;
        for (int j = 0; j < NMASK; ++j) {
            float vj = v[j];
            cnt += (vj > vi) || (vj == vi && j < i);   // top_k tie-break: lower index wins
        }
        keep[i] = (cnt < (NKEEP - 1)) ? 1 : 0;
    }
    __syncthreads();
    if (threadIdx.x == 0) {
        int* dm = g_dest + (size_t)row * NTOK;
        dm[0] = 0;
        int pos = 0;
        for (int i = 0; i < NMASK; ++i)
            dm[1 + i] = keep[i] ? (++pos) : -1;
    }
}

// ---------------- 128x128x16 tf32 mma.sync GEMM (unchanged from R5) -----------
template<int LDW, bool SCATTER, bool USE_AO>
__global__ __launch_bounds__(256, 2) void gemm_mma(const float* __restrict__ Ain,
                                                   const float* __restrict__ W,
                                                   const float* __restrict__ bias,
                                                   float* __restrict__ out)
{
    const float* __restrict__ A = USE_AO ? (const float*)g_ao : Ain;
    __shared__ float As[2][16][132];   // [stage][k][m], padded
    __shared__ float Bs[2][16][132];   // [stage][k][n], padded
    const int K = NC;

    int tid  = threadIdx.x;
    int brow = blockIdx.y * 128;
    int bcol = blockIdx.x * 128;

    int ar0 = tid >> 2;
    int ac  = (tid & 3) << 2;
    int br0 = tid >> 5;
    int bc  = (tid & 31) << 2;

    int wid  = tid >> 5;
    int lane = tid & 31;
    int gid  = lane >> 2;
    int tid4 = lane & 3;
    int m0 = (wid >> 2) * 64;
    int n0 = (wid & 3) * 32;

    bool aok0 = (brow + ar0)      < MROWS;
    bool aok1 = (brow + ar0 + 64) < MROWS;
    const float* Ap0 = A + (size_t)(brow + ar0) * K + ac;
    const float* Ap1 = Ap0 + (size_t)64 * K;
    const float* Wp  = W + (size_t)br0 * LDW + bcol + bc;

    const float4 z4 = make_float4(0.f, 0.f, 0.f, 0.f);
    float4 pa0 = aok0 ? *(const float4*)Ap0 : z4;
    float4 pa1 = aok1 ? *(const float4*)Ap1 : z4;
    float4 pb0 = *(const float4*)Wp;
    float4 pb1 = *(const float4*)(Wp + (size_t)8 * LDW);

    As[0][ac+0][ar0] = tf32_rna(pa0.x); As[0][ac+1][ar0] = tf32_rna(pa0.y);
    As[0][ac+2][ar0] = tf32_rna(pa0.z); As[0][ac+3][ar0] = tf32_rna(pa0.w);
    As[0][ac+0][ar0+64] = tf32_rna(pa1.x); As[0][ac+1][ar0+64] = tf32_rna(pa1.y);
    As[0][ac+2][ar0+64] = tf32_rna(pa1.z); As[0][ac+3][ar0+64] = tf32_rna(pa1.w);
    Bs[0][br0][bc+0]   = tf32_rna(pb0.x); Bs[0][br0][bc+1]   = tf32_rna(pb0.y);
    Bs[0][br0][bc+2]   = tf32_rna(pb0.z); Bs[0][br0][bc+3]   = tf32_rna(pb0.w);
    Bs[0][br0+8][bc+0] = tf32_rna(pb1.x); Bs[0][br0+8][bc+1] = tf32_rna(pb1.y);
    Bs[0][br0+8][bc+2] = tf32_rna(pb1.z); Bs[0][br0+8][bc+3] = tf32_rna(pb1.w);
    __syncthreads();

    float c[4][4][4];
    #pragma unroll
    for (int mt = 0; mt < 4; ++mt)
        #pragma unroll
        for (int nt = 0; nt < 4; ++nt)
            #pragma unroll
            for (int r = 0; r < 4; ++r) c[mt][nt][r] = 0.f;

    int buf = 0;
    for (int kt = 16; kt <= K; kt += 16) {
        bool more = kt < K;
        if (more) {
            pa0 = aok0 ? *(const float4*)(Ap0 + kt) : z4;
            pa1 = aok1 ? *(const float4*)(Ap1 + kt) : z4;
            pb0 = *(const float4*)(Wp + (size_t)kt * LDW);
            pb1 = *(const float4*)(Wp + (size_t)(kt + 8) * LDW);
        }
        #pragma unroll
        for (int ks = 0; ks < 2; ++ks) {
            const int kb = ks * 8;
            uint32_t bf[4][2], af[4][4];
            #pragma unroll
            for (int nt = 0; nt < 4; ++nt) {
                bf[nt][0] = __float_as_uint(Bs[buf][kb + tid4][n0 + nt*8 + gid]);
                bf[nt][1] = __float_as_uint(Bs[buf][kb + tid4 + 4][n0 + nt*8 + gid]);
            }
            #pragma unroll
            for (int mt = 0; mt < 4; ++mt) {
                af[mt][0] = __float_as_uint(As[buf][kb + tid4][m0 + mt*16 + gid]);
                af[mt][1] = __float_as_uint(As[buf][kb + tid4][m0 + mt*16 + gid + 8]);
                af[mt][2] = __float_as_uint(As[buf][kb + tid4 + 4][m0 + mt*16 + gid]);
                af[mt][3] = __float_as_uint(As[buf][kb + tid4 + 4][m0 + mt*16 + gid + 8]);
            }
            #pragma unroll
            for (int mt = 0; mt < 4; ++mt)
                #pragma unroll
                for (int nt = 0; nt < 4; ++nt)
                    mma_tf32(c[mt][nt], af[mt], bf[nt]);
        }
        if (more) {
            int nb = buf ^ 1;
            As[nb][ac+0][ar0] = tf32_rna(pa0.x); As[nb][ac+1][ar0] = tf32_rna(pa0.y);
            As[nb][ac+2][ar0] = tf32_rna(pa0.z); As[nb][ac+3][ar0] = tf32_rna(pa0.w);
            As[nb][ac+0][ar0+64] = tf32_rna(pa1.x); As[nb][ac+1][ar0+64] = tf32_rna(pa1.y);
            As[nb][ac+2][ar0+64] = tf32_rna(pa1.z); As[nb][ac+3][ar0+64] = tf32_rna(pa1.w);
            Bs[nb][br0][bc+0]   = tf32_rna(pb0.x); Bs[nb][br0][bc+1]   = tf32_rna(pb0.y);
            Bs[nb][br0][bc+2]   = tf32_rna(pb0.z); Bs[nb][br0][bc+3]   = tf32_rna(pb0.w);
            Bs[nb][br0+8][bc+0] = tf32_rna(pb1.x); Bs[nb][br0+8][bc+1] = tf32_rna(pb1.y);
            Bs[nb][br0+8][bc+2] = tf32_rna(pb1.z); Bs[nb][br0+8][bc+3] = tf32_rna(pb1.w);
            __syncthreads();
            buf = nb;
        }
    }

    int colbase = bcol + n0;
    int s  = colbase / NC;
    int hd = colbase - s * NC;
    int h  = hd >> 6;

    #pragma unroll
    for (int mt = 0; mt < 4; ++mt) {
        #pragma unroll
        for (int half = 0; half < 2; ++half) {
            int m = brow + m0 + mt * 16 + gid + half * 8;
            if (m >= MROWS) continue;
            float* dst = nullptr;
            int d_off = 0;
            if (SCATTER) {
                int b  = m / NTOK;
                int n  = m - b * NTOK;
                int bh = b * NHEAD + h;
                if (s == 0) {
                    dst = &g_q[((size_t)bh * NTOK + n) * ND];
                } else {
                    int dest = g_dest[bh * NTOK + n];
                    if (dest >= 0)
                        dst = &((s == 1) ? g_kp : g_vp)[((size_t)bh * NKEEP + dest) * ND];
                }
                d_off = hd & 63;
            } else {
                dst = out + (size_t)m * LDW + colbase;
            }
            if (!dst) continue;
            #pragma unroll
            for (int nt = 0; nt < 4; ++nt) {
                int cl = nt * 8 + tid4 * 2;
                float2 bv = *(const float2*)(bias + colbase + cl);
                float2 o;
                o.x = c[mt][nt][half * 2 + 0] + bv.x;
                o.y = c[mt][nt][half * 2 + 1] + bv.y;
                *(float2*)(dst + (SCATTER ? d_off : 0) + cl) = o;
            }
        }
    }
}

// ---------------- attention: ONE CTA per (b,h); KV staged once -----------------
// Strides: Qs/Ks 68 (=4 mod 32), Vs 72, Ss 300 — conflict-free fragment access.
#define QS_STR 68
#define KS_STR 68
#define VS_STR 72
#define SS_STR 300
#define ATTN_SMEM ((32*QS_STR + NPAD*KS_STR + NPAD*VS_STR + 32*SS_STR) * 4)

__global__ __launch_bounds__(256) void attn_mma()
{
    extern __shared__ float sh[];
    float* Qs = sh;                        // 32 x 68
    float* Ks = Qs + 32 * QS_STR;          // 296 x 68
    float* Vs = Ks + NPAD * KS_STR;        // 296 x 72
    float* Ss = Vs + NPAD * VS_STR;        // 32 x 300

    int tid  = threadIdx.x;
    int bh   = blockIdx.x;
    int wid  = tid >> 5;
    int lane = tid & 31;
    int gid  = lane >> 2;
    int t4   = lane & 3;

    // ---- stage K/V ONCE (tf32-rounded, pad rows zeroed) ----
    const float* kp = g_kp + (size_t)bh * NKEEP * ND;
    const float* vp = g_vp + (size_t)bh * NKEEP * ND;
    for (int idx = tid; idx < NPAD * ND; idx += 256) {
        int m = idx >> 6, d = idx & 63;
        float kv = 0.f, vv = 0.f;
        if (m < NKEEP) {
            kv = tf32_rna(kp[(size_t)m * ND + d]);
            vv = tf32_rna(vp[(size_t)m * ND + d]);
        }
        Ks[m * KS_STR + d] = kv;
        Vs[m * VS_STR + d] = vv;
    }
    const float* qp = g_q + (size_t)bh * NTOK * ND;
    int b = bh / NHEAD, h = bh - b * NHEAD;

    // ---- loop over 19 query tiles ----
    for (int q0 = 0; q0 < NTOK; q0 += 32) {
        // load Q tile
        for (int idx = tid; idx < 32 * ND; idx += 256) {
            int qq = idx >> 6, d = idx & 63;
            int qg = q0 + qq;
            Qs[qq * QS_STR + d] = (qg < NTOK) ? tf32_rna(qp[(size_t)qg * ND + d]) : 0.f;
        }
        __syncthreads();

        // Phase A: S = (Q K^T) * scale
        {
            int wm = wid & 1, wn = wid >> 1;
            int m0 = wm * 16;
            for (int nt = wn; nt < NT8; nt += 4) {
                int nb = nt * 8;
                float c[4] = {0.f, 0.f, 0.f, 0.f};
                #pragma unroll
                for (int ks = 0; ks < 8; ++ks) {
                    int k0 = ks * 8;
                    uint32_t a[4], bb[2];
                    a[0] = __float_as_uint(Qs[(m0 + gid) * QS_STR + k0 + t4]);
                    a[1] = __float_as_uint(Qs[(m0 + gid + 8) * QS_STR + k0 + t4]);
                    a[2] = __float_as_uint(Qs[(m0 + gid) * QS_STR + k0 + t4 + 4]);
                    a[3] = __float_as_uint(Qs[(m0 + gid + 8) * QS_STR + k0 + t4 + 4]);
                    bb[0] = __float_as_uint(Ks[(nb + gid) * KS_STR + k0 + t4]);
                    bb[1] = __float_as_uint(Ks[(nb + gid) * KS_STR + k0 + t4 + 4]);
                    mma_tf32(c, a, bb);
                }
                *(float2*)&Ss[(m0 + gid) * SS_STR + nb + 2 * t4]
                    = make_float2(c[0] * 0.125f, c[1] * 0.125f);
                *(float2*)&Ss[(m0 + gid + 8) * SS_STR + nb + 2 * t4]
                    = make_float2(c[2] * 0.125f, c[3] * 0.125f);
            }
        }
        __syncthreads();

        // Phase B: row softmax over first NKEEP cols
        {
            int w = tid >> 5, ln = tid & 31;
            #pragma unroll
            for (int r = 0; r < 4; ++r) {
                float* Sr = Ss + (w * 4 + r) * SS_STR;
                float mx = -3.0e38f;
                for (int m = ln; m < NKEEP; m += 32) mx = fmaxf(mx, Sr[m]);
                #pragma unroll
                for (int o = 16; o; o >>= 1) mx = fmaxf(mx, __shfl_xor_sync(0xffffffffu, mx, o));
                float sum = 0.f;
                for (int m = ln; m < NKEEP; m += 32) {
                    float e = __expf(Sr[m] - mx);
                    Sr[m] = e;
                    sum += e;
                }
                #pragma unroll
                for (int o = 16; o; o >>= 1) sum += __shfl_xor_sync(0xffffffffu, sum, o);
                float inv = 1.f / sum;
                for (int m = ln; m < NKEEP; m += 32) Sr[m] *= inv;
            }
        }
        __syncthreads();

        // Phase C: O = P @ V
        {
            int wm = wid & 1, wn = wid >> 1;
            int m0 = wm * 16, n0 = wn * 16;
            float c[2][4];
            #pragma unroll
            for (int nt = 0; nt < 2; ++nt)
                #pragma unroll
                for (int r = 0; r < 4; ++r) c[nt][r] = 0.f;

            for (int ks = 0; ks < NT8; ++ks) {
                int k0 = ks * 8;
                uint32_t a[4];
                a[0] = __float_as_uint(tf32_rna(Ss[(m0 + gid) * SS_STR + k0 + t4]));
                a[1] = __float_as_uint(tf32_rna(Ss[(m0 + gid + 8) * SS_STR + k0 + t4]));
                a[2] = __float_as_uint(tf32_rna(Ss[(m0 + gid) * SS_STR + k0 + t4 + 4]));
                a[3] = __float_as_uint(tf32_rna(Ss[(m0 + gid + 8) * SS_STR + k0 + t4 + 4]));
                #pragma unroll
                for (int nt = 0; nt < 2; ++nt) {
                    uint32_t bb[2];
                    bb[0] = __float_as_uint(Vs[(k0 + t4) * VS_STR + n0 + nt * 8 + gid]);
                    bb[1] = __float_as_uint(Vs[(k0 + t4 + 4) * VS_STR + n0 + nt * 8 + gid]);
                    mma_tf32(c[nt], a, bb);
                }
            }

            #pragma unroll
            for (int half = 0; half < 2; ++half) {
                int qg = q0 + m0 + gid + half * 8;
                if (qg >= NTOK) continue;
                float* dst = &g_ao[((size_t)(b * NTOK + qg)) * NC + h * ND + n0];
                #pragma unroll
                for (int nt = 0; nt < 2; ++nt) {
                    float2 o;
                    o.x = c[nt][half * 2 + 0];
                    o.y = c[nt][half * 2 + 1];
                    *(float2*)(dst + nt * 8 + 2 * t4) = o;
                }
            }
        }
        __syncthreads();   // Ss/Qs reused next iteration
    }
}

// ---------------- launch -------------------------------------------------------
extern "C" void kernel_launch(void* const* d_in, const int* in_sizes, int n_in,
                              void* d_out, int out_size)
{
    const float* x     = (const float*)d_in[0];
    const float* mask  = (const float*)d_in[1];
    const float* Wqkv  = (const float*)d_in[2];
    const float* bqkv  = (const float*)d_in[3];
    const float* Wproj = (const float*)d_in[4];
    const float* bproj = (const float*)d_in[5];
    float* out = (float*)d_out;

    select_kernel<<<NB * NHEAD, 256>>>(mask);

    dim3 g1(QCOLS / 128, (MROWS + 127) / 128);
    gemm_mma<QCOLS, true, false><<<g1, 256>>>(x, Wqkv, bqkv, nullptr);

    cudaFuncSetAttribute(attn_mma, cudaFuncAttributeMaxDynamicSharedMemorySize, ATTN_SMEM);
    attn_mma<<<NB * NHEAD, 256, ATTN_SMEM>>>();

    dim3 g2(NC / 128, (MROWS + 127) / 128);
    gemm_mma<NC, false, true><<<g2, 256>>>(nullptr, Wproj, bproj, out);
}

// round 8
// speedup vs baseline: 1.7363x; 1.1208x over previous
#include <cuda_runtime.h>
#include <cstdint>

#define NHEAD 12
#define NB    64
#define NTOK  577
#define NC    768
#define ND    64
#define NKEEP 289          // tokens kept incl. CLS
#define NMASK 576
#define MROWS (NB*NTOK)    // 36928
#define QCOLS (3*NC)       // 2304
#define NPAD  296          // padded kept-token count (37 x 8)
#define NT8   37           // n-tiles of 8 in padded token dim

// ---------------- scratch (static device globals; no allocations) -------------
__device__ __align__(16) float g_q [(size_t)NB*NHEAD*NTOK*ND];   // [B,H,N,D]
__device__ __align__(16) float g_kp[(size_t)NB*NHEAD*NKEEP*ND];  // gathered K
__device__ __align__(16) float g_vp[(size_t)NB*NHEAD*NKEEP*ND];  // gathered V
__device__ __align__(16) float g_ao[(size_t)NB*NTOK*NC];         // attn out [B,N,C]
__device__ int g_dest[NB*NHEAD*NTOK];                            // token -> kept slot (-1 = dropped)

// ---------------- helpers ------------------------------------------------------
__device__ __forceinline__ float tf32_rna(float v) {
    uint32_t u;
    asm("cvt.rna.tf32.f32 %0, %1;" : "=r"(u) : "f"(v));
    return __uint_as_float(u);
}
__device__ __forceinline__ void mma_tf32(float* c, const uint32_t* a, const uint32_t* b) {
    asm volatile(
        "mma.sync.aligned.m16n8k8.row.col.f32.tf32.tf32.f32 "
        "{%0,%1,%2,%3}, {%4,%5,%6,%7}, {%8,%9}, {%0,%1,%2,%3};\n"
        : "+f"(c[0]), "+f"(c[1]), "+f"(c[2]), "+f"(c[3])
        : "r"(a[0]), "r"(a[1]), "r"(a[2]), "r"(a[3]), "r"(b[0]), "r"(b[1]));
}

// ---------------- token selection: exact top-288 of 576 per (b,h) -------------
__global__ __launch_bounds__(256) void select_kernel(const float* __restrict__ mask)
{
    int row = blockIdx.x;                       // b*NHEAD + h
    __shared__ float v[NMASK];
    __shared__ unsigned char keep[NMASK];
    const float* mrow = mask + (size_t)row * NMASK;
    for (int i = threadIdx.x; i < NMASK; i += 256) v[i] = mrow[i];
    __syncthreads();
    for (int i = threadIdx.x; i < NMASK; i += 256) {
        float vi = v[i];
        int cnt = 0;
        for (int j = 0; j < NMASK; ++j) {
            float vj = v[j];
            cnt += (vj > vi) || (vj == vi && j < i);   // top_k tie-break: lower index wins
        }
        keep[i] = (cnt < (NKEEP - 1)) ? 1 : 0;
    }
    __syncthreads();
    if (threadIdx.x == 0) {
        int* dm = g_dest + (size_t)row * NTOK;
        dm[0] = 0;
        int pos = 0;
        for (int i = 0; i < NMASK; ++i)
            dm[1 + i] = keep[i] ? (++pos) : -1;
    }
}

// ---------------- 128x128x16 tf32 mma.sync GEMM, conflict-free smem ------------
// As: [m][k] stride 20 (bank pattern gid*20+t4 -> 32 distinct), STS.128 stores.
// Bs: [k][n] stride 136 (t4*8+gid -> 32 distinct), STS.128 stores (k row uniform).
#define AS_STR 20
#define BS_STR 136
template<int LDW, bool SCATTER, bool USE_AO>
__global__ __launch_bounds__(256, 2) void gemm_mma(const float* __restrict__ Ain,
                                                   const float* __restrict__ W,
                                                   const float* __restrict__ bias,
                                                   float* __restrict__ out)
{
    const float* __restrict__ A = USE_AO ? (const float*)g_ao : Ain;
    __shared__ float As[2][128][AS_STR];   // [stage][m][k], 16 k + 4 pad
    __shared__ float Bs[2][16][BS_STR];    // [stage][k][n], 128 n + 8 pad
    const int K = NC;

    int tid  = threadIdx.x;
    int brow = blockIdx.y * 128;
    int bcol = blockIdx.x * 128;

    int ar0 = tid >> 2;          // 0..63 (rows ar0, ar0+64)
    int ac  = (tid & 3) << 2;    // k-offset 0,4,8,12
    int br0 = tid >> 5;          // 0..7  (k rows br0, br0+8)
    int bc  = (tid & 31) << 2;   // col offset

    int wid  = tid >> 5;
    int lane = tid & 31;
    int gid  = lane >> 2;
    int tid4 = lane & 3;
    int m0 = (wid >> 2) * 64;
    int n0 = (wid & 3) * 32;

    bool aok0 = (brow + ar0)      < MROWS;
    bool aok1 = (brow + ar0 + 64) < MROWS;
    const float* Ap0 = A + (size_t)(brow + ar0) * K + ac;
    const float* Ap1 = Ap0 + (size_t)64 * K;
    const float* Wp  = W + (size_t)br0 * LDW + bcol + bc;

    const float4 z4 = make_float4(0.f, 0.f, 0.f, 0.f);
    float4 pa0 = aok0 ? *(const float4*)Ap0 : z4;
    float4 pa1 = aok1 ? *(const float4*)Ap1 : z4;
    float4 pb0 = *(const float4*)Wp;
    float4 pb1 = *(const float4*)(Wp + (size_t)8 * LDW);

    {
        float4 t0 = make_float4(tf32_rna(pa0.x), tf32_rna(pa0.y), tf32_rna(pa0.z), tf32_rna(pa0.w));
        float4 t1 = make_float4(tf32_rna(pa1.x), tf32_rna(pa1.y), tf32_rna(pa1.z), tf32_rna(pa1.w));
        *(float4*)&As[0][ar0][ac]      = t0;
        *(float4*)&As[0][ar0 + 64][ac] = t1;
        float4 u0 = make_float4(tf32_rna(pb0.x), tf32_rna(pb0.y), tf32_rna(pb0.z), tf32_rna(pb0.w));
        float4 u1 = make_float4(tf32_rna(pb1.x), tf32_rna(pb1.y), tf32_rna(pb1.z), tf32_rna(pb1.w));
        *(float4*)&Bs[0][br0][bc]     = u0;
        *(float4*)&Bs[0][br0 + 8][bc] = u1;
    }
    __syncthreads();

    float c[4][4][4];
    #pragma unroll
    for (int mt = 0; mt < 4; ++mt)
        #pragma unroll
        for (int nt = 0; nt < 4; ++nt)
            #pragma unroll
            for (int r = 0; r < 4; ++r) c[mt][nt][r] = 0.f;

    int buf = 0;
    for (int kt = 16; kt <= K; kt += 16) {
        bool more = kt < K;
        if (more) {
            pa0 = aok0 ? *(const float4*)(Ap0 + kt) : z4;
            pa1 = aok1 ? *(const float4*)(Ap1 + kt) : z4;
            pb0 = *(const float4*)(Wp + (size_t)kt * LDW);
            pb1 = *(const float4*)(Wp + (size_t)(kt + 8) * LDW);
        }
        #pragma unroll
        for (int ks = 0; ks < 2; ++ks) {
            const int kb = ks * 8;
            uint32_t bf[4][2], af[4][4];
            #pragma unroll
            for (int nt = 0; nt < 4; ++nt) {
                bf[nt][0] = __float_as_uint(Bs[buf][kb + tid4][n0 + nt*8 + gid]);
                bf[nt][1] = __float_as_uint(Bs[buf][kb + tid4 + 4][n0 + nt*8 + gid]);
            }
            #pragma unroll
            for (int mt = 0; mt < 4; ++mt) {
                af[mt][0] = __float_as_uint(As[buf][m0 + mt*16 + gid][kb + tid4]);
                af[mt][1] = __float_as_uint(As[buf][m0 + mt*16 + gid + 8][kb + tid4]);
                af[mt][2] = __float_as_uint(As[buf][m0 + mt*16 + gid][kb + tid4 + 4]);
                af[mt][3] = __float_as_uint(As[buf][m0 + mt*16 + gid + 8][kb + tid4 + 4]);
            }
            #pragma unroll
            for (int mt = 0; mt < 4; ++mt)
                #pragma unroll
                for (int nt = 0; nt < 4; ++nt)
                    mma_tf32(c[mt][nt], af[mt], bf[nt]);
        }
        if (more) {
            int nb = buf ^ 1;
            float4 t0 = make_float4(tf32_rna(pa0.x), tf32_rna(pa0.y), tf32_rna(pa0.z), tf32_rna(pa0.w));
            float4 t1 = make_float4(tf32_rna(pa1.x), tf32_rna(pa1.y), tf32_rna(pa1.z), tf32_rna(pa1.w));
            *(float4*)&As[nb][ar0][ac]      = t0;
            *(float4*)&As[nb][ar0 + 64][ac] = t1;
            float4 u0 = make_float4(tf32_rna(pb0.x), tf32_rna(pb0.y), tf32_rna(pb0.z), tf32_rna(pb0.w));
            float4 u1 = make_float4(tf32_rna(pb1.x), tf32_rna(pb1.y), tf32_rna(pb1.z), tf32_rna(pb1.w));
            *(float4*)&Bs[nb][br0][bc]     = u0;
            *(float4*)&Bs[nb][br0 + 8][bc] = u1;
            __syncthreads();
            buf = nb;
        }
    }

    int colbase = bcol + n0;
    int s  = colbase / NC;
    int hd = colbase - s * NC;
    int h  = hd >> 6;

    #pragma unroll
    for (int mt = 0; mt < 4; ++mt) {
        #pragma unroll
        for (int half = 0; half < 2; ++half) {
            int m = brow + m0 + mt * 16 + gid + half * 8;
            if (m >= MROWS) continue;
            float* dst = nullptr;
            int d_off = 0;
            if (SCATTER) {
                int b  = m / NTOK;
                int n  = m - b * NTOK;
                int bh = b * NHEAD + h;
                if (s == 0) {
                    dst = &g_q[((size_t)bh * NTOK + n) * ND];
                } else {
                    int dest = g_dest[bh * NTOK + n];
                    if (dest >= 0)
                        dst = &((s == 1) ? g_kp : g_vp)[((size_t)bh * NKEEP + dest) * ND];
                }
                d_off = hd & 63;
            } else {
                dst = out + (size_t)m * LDW + colbase;
            }
            if (!dst) continue;
            #pragma unroll
            for (int nt = 0; nt < 4; ++nt) {
                int cl = nt * 8 + tid4 * 2;
                float2 bv = *(const float2*)(bias + colbase + cl);
                float2 o;
                o.x = c[mt][nt][half * 2 + 0] + bv.x;
                o.y = c[mt][nt][half * 2 + 1] + bv.y;
                *(float2*)(dst + (SCATTER ? d_off : 0) + cl) = o;
            }
        }
    }
}

// ---------------- attention: ONE CTA per (b,h); KV staged once -----------------
#define QS_STR 68
#define KS_STR 68
#define VS_STR 72
#define SS_STR 300
#define ATTN_SMEM ((32*QS_STR + NPAD*KS_STR + NPAD*VS_STR + 32*SS_STR) * 4)

__global__ __launch_bounds__(256) void attn_mma()
{
    extern __shared__ float sh[];
    float* Qs = sh;                        // 32 x 68
    float* Ks = Qs + 32 * QS_STR;          // 296 x 68
    float* Vs = Ks + NPAD * KS_STR;        // 296 x 72
    float* Ss = Vs + NPAD * VS_STR;        // 32 x 300

    int tid  = threadIdx.x;
    int bh   = blockIdx.x;
    int wid  = tid >> 5;
    int lane = tid & 31;
    int gid  = lane >> 2;
    int t4   = lane & 3;

    const float* kp = g_kp + (size_t)bh * NKEEP * ND;
    const float* vp = g_vp + (size_t)bh * NKEEP * ND;
    for (int idx = tid; idx < NPAD * ND; idx += 256) {
        int m = idx >> 6, d = idx & 63;
        float kv = 0.f, vv = 0.f;
        if (m < NKEEP) {
            kv = tf32_rna(kp[(size_t)m * ND + d]);
            vv = tf32_rna(vp[(size_t)m * ND + d]);
        }
        Ks[m * KS_STR + d] = kv;
        Vs[m * VS_STR + d] = vv;
    }
    const float* qp = g_q + (size_t)bh * NTOK * ND;
    int b = bh / NHEAD, h = bh - b * NHEAD;

    for (int q0 = 0; q0 < NTOK; q0 += 32) {
        for (int idx = tid; idx < 32 * ND; idx += 256) {
            int qq = idx >> 6, d = idx & 63;
            int qg = q0 + qq;
            Qs[qq * QS_STR + d] = (qg < NTOK) ? tf32_rna(qp[(size_t)qg * ND + d]) : 0.f;
        }
        __syncthreads();

        // Phase A: S = (Q K^T) * scale
        {
            int wm = wid & 1, wn = wid >> 1;
            int m0 = wm * 16;
            for (int nt = wn; nt < NT8; nt += 4) {
                int nb = nt * 8;
                float c[4] = {0.f, 0.f, 0.f, 0.f};
                #pragma unroll
                for (int ks = 0; ks < 8; ++ks) {
                    int k0 = ks * 8;
                    uint32_t a[4], bb[2];
                    a[0] = __float_as_uint(Qs[(m0 + gid) * QS_STR + k0 + t4]);
                    a[1] = __float_as_uint(Qs[(m0 + gid + 8) * QS_STR + k0 + t4]);
                    a[2] = __float_as_uint(Qs[(m0 + gid) * QS_STR + k0 + t4 + 4]);
                    a[3] = __float_as_uint(Qs[(m0 + gid + 8) * QS_STR + k0 + t4 + 4]);
                    bb[0] = __float_as_uint(Ks[(nb + gid) * KS_STR + k0 + t4]);
                    bb[1] = __float_as_uint(Ks[(nb + gid) * KS_STR + k0 + t4 + 4]);
                    mma_tf32(c, a, bb);
                }
                *(float2*)&Ss[(m0 + gid) * SS_STR + nb + 2 * t4]
                    = make_float2(c[0] * 0.125f, c[1] * 0.125f);
                *(float2*)&Ss[(m0 + gid + 8) * SS_STR + nb + 2 * t4]
                    = make_float2(c[2] * 0.125f, c[3] * 0.125f);
            }
        }
        __syncthreads();

        // Phase B: row softmax
        {
            int w = tid >> 5, ln = tid & 31;
            #pragma unroll
            for (int r = 0; r < 4; ++r) {
                float* Sr = Ss + (w * 4 + r) * SS_STR;
                float mx = -3.0e38f;
                for (int m = ln; m < NKEEP; m += 32) mx = fmaxf(mx, Sr[m]);
                #pragma unroll
                for (int o = 16; o; o >>= 1) mx = fmaxf(mx, __shfl_xor_sync(0xffffffffu, mx, o));
                float sum = 0.f;
                for (int m = ln; m < NKEEP; m += 32) {
                    float e = __expf(Sr[m] - mx);
                    Sr[m] = e;
                    sum += e;
                }
                #pragma unroll
                for (int o = 16; o; o >>= 1) sum += __shfl_xor_sync(0xffffffffu, sum, o);
                float inv = 1.f / sum;
                for (int m = ln; m < NKEEP; m += 32) Sr[m] *= inv;
            }
        }
        __syncthreads();

        // Phase C: O = P @ V
        {
            int wm = wid & 1, wn = wid >> 1;
            int m0 = wm * 16, n0 = wn * 16;
            float c[2][4];
            #pragma unroll
            for (int nt = 0; nt < 2; ++nt)
                #pragma unroll
                for (int r = 0; r < 4; ++r) c[nt][r] = 0.f;

            for (int ks = 0; ks < NT8; ++ks) {
                int k0 = ks * 8;
                uint32_t a[4];
                a[0] = __float_as_uint(tf32_rna(Ss[(m0 + gid) * SS_STR + k0 + t4]));
                a[1] = __float_as_uint(tf32_rna(Ss[(m0 + gid + 8) * SS_STR + k0 + t4]));
                a[2] = __float_as_uint(tf32_rna(Ss[(m0 + gid) * SS_STR + k0 + t4 + 4]));
                a[3] = __float_as_uint(tf32_rna(Ss[(m0 + gid + 8) * SS_STR + k0 + t4 + 4]));
                #pragma unroll
                for (int nt = 0; nt < 2; ++nt) {
                    uint32_t bb[2];
                    bb[0] = __float_as_uint(Vs[(k0 + t4) * VS_STR + n0 + nt * 8 + gid]);
                    bb[1] = __float_as_uint(Vs[(k0 + t4 + 4) * VS_STR + n0 + nt * 8 + gid]);
                    mma_tf32(c[nt], a, bb);
                }
            }

            #pragma unroll
            for (int half = 0; half < 2; ++half) {
                int qg = q0 + m0 + gid + half * 8;
                if (qg >= NTOK) continue;
                float* dst = &g_ao[((size_t)(b * NTOK + qg)) * NC + h * ND + n0];
                #pragma unroll
                for (int nt = 0; nt < 2; ++nt) {
                    float2 o;
                    o.x = c[nt][half * 2 + 0];
                    o.y = c[nt][half * 2 + 1];
                    *(float2*)(dst + nt * 8 + 2 * t4) = o;
                }
            }
        }
        __syncthreads();
    }
}

// ---------------- launch -------------------------------------------------------
extern "C" void kernel_launch(void* const* d_in, const int* in_sizes, int n_in,
                              void* d_out, int out_size)
{
    const float* x     = (const float*)d_in[0];
    const float* mask  = (const float*)d_in[1];
    const float* Wqkv  = (const float*)d_in[2];
    const float* bqkv  = (const float*)d_in[3];
    const float* Wproj = (const float*)d_in[4];
    const float* bproj = (const float*)d_in[5];
    float* out = (float*)d_out;

    select_kernel<<<NB * NHEAD, 256>>>(mask);

    dim3 g1(QCOLS / 128, (MROWS + 127) / 128);
    gemm_mma<QCOLS, true, false><<<g1, 256>>>(x, Wqkv, bqkv, nullptr);

    cudaFuncSetAttribute(attn_mma, cudaFuncAttributeMaxDynamicSharedMemorySize, ATTN_SMEM);
    attn_mma<<<NB * NHEAD, 256, ATTN_SMEM>>>();

    dim3 g2(NC / 128, (MROWS + 127) / 128);
    gemm_mma<NC, false, true><<<g2, 256>>>(nullptr, Wproj, bproj, out);
}

// round 9
// speedup vs baseline: 2.0230x; 1.1652x over previous
#include <cuda_runtime.h>
#include <cstdint>

#define NHEAD 12
#define NB    64
#define NTOK  577
#define NC    768
#define ND    64
#define NKEEP 289          // tokens kept incl. CLS
#define NMASK 576
#define MROWS (NB*NTOK)    // 36928
#define QCOLS (3*NC)       // 2304
#define NPAD  296          // padded kept-token count (37 x 8)
#define NT8   37           // n-tiles of 8 in padded token dim

// ---------------- scratch (static device globals; no allocations) -------------
__device__ __align__(16) float g_q [(size_t)NB*NHEAD*NTOK*ND];   // [B,H,N,D]
__device__ __align__(16) float g_kp[(size_t)NB*NHEAD*NKEEP*ND];  // gathered K
__device__ __align__(16) float g_vp[(size_t)NB*NHEAD*NKEEP*ND];  // gathered V
__device__ __align__(16) float g_ao[(size_t)NB*NTOK*NC];         // attn out [B,N,C]
__device__ int g_dest[NB*NHEAD*NTOK];                            // token -> kept slot (-1 = dropped)

// ---------------- helpers ------------------------------------------------------
__device__ __forceinline__ float tf32_rna(float v) {
    uint32_t u;
    asm("cvt.rna.tf32.f32 %0, %1;" : "=r"(u) : "f"(v));
    return __uint_as_float(u);
}
__device__ __forceinline__ void mma_tf32(float* c, const uint32_t* a, const uint32_t* b) {
    asm volatile(
        "mma.sync.aligned.m16n8k8.row.col.f32.tf32.tf32.f32 "
        "{%0,%1,%2,%3}, {%4,%5,%6,%7}, {%8,%9}, {%0,%1,%2,%3};\n"
        : "+f"(c[0]), "+f"(c[1]), "+f"(c[2]), "+f"(c[3])
        : "r"(a[0]), "r"(a[1]), "r"(a[2]), "r"(a[3]), "r"(b[0]), "r"(b[1]));
}

// ---------------- token selection: exact top-288 of 576 per (b,h) -------------
__global__ __launch_bounds__(256) void select_kernel(const float* __restrict__ mask)
{
    int row = blockIdx.x;                       // b*NHEAD + h
    __shared__ float v[NMASK];
    __shared__ unsigned char keep[NMASK];
    const float* mrow = mask + (size_t)row * NMASK;
    for (int i = threadIdx.x; i < NMASK; i += 256) v[i] = mrow[i];
    __syncthreads();
    for (int i = threadIdx.x; i < NMASK; i += 256) {
        float vi = v[i];
        int cnt = 0;
        for (int j = 0; j < NMASK; ++j) {
            float vj = v[j];
            cnt += (vj > vi) || (vj == vi && j < i);   // top_k tie-break: lower index wins
        }
        keep[i] = (cnt < (NKEEP - 1)) ? 1 : 0;
    }
    __syncthreads();
    if (threadIdx.x == 0) {
        int* dm = g_dest + (size_t)row * NTOK;
        dm[0] = 0;
        int pos = 0;
        for (int i = 0; i < NMASK; ++i)
            dm[1 + i] = keep[i] ? (++pos) : -1;
    }
}

// ---------------- 128x128x16 tf32 mma.sync GEMM, conflict-free smem ------------
#define AS_STR 20
#define BS_STR 136
template<int LDW, bool SCATTER, bool USE_AO>
__global__ __launch_bounds__(256, 2) void gemm_mma(const float* __restrict__ Ain,
                                                   const float* __restrict__ W,
                                                   const float* __restrict__ bias,
                                                   float* __restrict__ out)
{
    const float* __restrict__ A = USE_AO ? (const float*)g_ao : Ain;
    __shared__ float As[2][128][AS_STR];   // [stage][m][k], 16 k + 4 pad
    __shared__ float Bs[2][16][BS_STR];    // [stage][k][n], 128 n + 8 pad
    const int K = NC;

    int tid  = threadIdx.x;
    int brow = blockIdx.y * 128;
    int bcol = blockIdx.x * 128;

    int ar0 = tid >> 2;
    int ac  = (tid & 3) << 2;
    int br0 = tid >> 5;
    int bc  = (tid & 31) << 2;

    int wid  = tid >> 5;
    int lane = tid & 31;
    int gid  = lane >> 2;
    int tid4 = lane & 3;
    int m0 = (wid >> 2) * 64;
    int n0 = (wid & 3) * 32;

    bool aok0 = (brow + ar0)      < MROWS;
    bool aok1 = (brow + ar0 + 64) < MROWS;
    const float* Ap0 = A + (size_t)(brow + ar0) * K + ac;
    const float* Ap1 = Ap0 + (size_t)64 * K;
    const float* Wp  = W + (size_t)br0 * LDW + bcol + bc;

    const float4 z4 = make_float4(0.f, 0.f, 0.f, 0.f);
    float4 pa0 = aok0 ? *(const float4*)Ap0 : z4;
    float4 pa1 = aok1 ? *(const float4*)Ap1 : z4;
    float4 pb0 = *(const float4*)Wp;
    float4 pb1 = *(const float4*)(Wp + (size_t)8 * LDW);

    {
        float4 t0 = make_float4(tf32_rna(pa0.x), tf32_rna(pa0.y), tf32_rna(pa0.z), tf32_rna(pa0.w));
        float4 t1 = make_float4(tf32_rna(pa1.x), tf32_rna(pa1.y), tf32_rna(pa1.z), tf32_rna(pa1.w));
        *(float4*)&As[0][ar0][ac]      = t0;
        *(float4*)&As[0][ar0 + 64][ac] = t1;
        float4 u0 = make_float4(tf32_rna(pb0.x), tf32_rna(pb0.y), tf32_rna(pb0.z), tf32_rna(pb0.w));
        float4 u1 = make_float4(tf32_rna(pb1.x), tf32_rna(pb1.y), tf32_rna(pb1.z), tf32_rna(pb1.w));
        *(float4*)&Bs[0][br0][bc]     = u0;
        *(float4*)&Bs[0][br0 + 8][bc] = u1;
    }
    __syncthreads();

    float c[4][4][4];
    #pragma unroll
    for (int mt = 0; mt < 4; ++mt)
        #pragma unroll
        for (int nt = 0; nt < 4; ++nt)
            #pragma unroll
            for (int r = 0; r < 4; ++r) c[mt][nt][r] = 0.f;

    int buf = 0;
    for (int kt = 16; kt <= K; kt += 16) {
        bool more = kt < K;
        if (more) {
            pa0 = aok0 ? *(const float4*)(Ap0 + kt) : z4;
            pa1 = aok1 ? *(const float4*)(Ap1 + kt) : z4;
            pb0 = *(const float4*)(Wp + (size_t)kt * LDW);
            pb1 = *(const float4*)(Wp + (size_t)(kt + 8) * LDW);
        }
        #pragma unroll
        for (int ks = 0; ks < 2; ++ks) {
            const int kb = ks * 8;
            uint32_t bf[4][2], af[4][4];
            #pragma unroll
            for (int nt = 0; nt < 4; ++nt) {
                bf[nt][0] = __float_as_uint(Bs[buf][kb + tid4][n0 + nt*8 + gid]);
                bf[nt][1] = __float_as_uint(Bs[buf][kb + tid4 + 4][n0 + nt*8 + gid]);
            }
            #pragma unroll
            for (int mt = 0; mt < 4; ++mt) {
                af[mt][0] = __float_as_uint(As[buf][m0 + mt*16 + gid][kb + tid4]);
                af[mt][1] = __float_as_uint(As[buf][m0 + mt*16 + gid + 8][kb + tid4]);
                af[mt][2] = __float_as_uint(As[buf][m0 + mt*16 + gid][kb + tid4 + 4]);
                af[mt][3] = __float_as_uint(As[buf][m0 + mt*16 + gid + 8][kb + tid4 + 4]);
            }
            #pragma unroll
            for (int mt = 0; mt < 4; ++mt)
                #pragma unroll
                for (int nt = 0; nt < 4; ++nt)
                    mma_tf32(c[mt][nt], af[mt], bf[nt]);
        }
        if (more) {
            int nb = buf ^ 1;
            float4 t0 = make_float4(tf32_rna(pa0.x), tf32_rna(pa0.y), tf32_rna(pa0.z), tf32_rna(pa0.w));
            float4 t1 = make_float4(tf32_rna(pa1.x), tf32_rna(pa1.y), tf32_rna(pa1.z), tf32_rna(pa1.w));
            *(float4*)&As[nb][ar0][ac]      = t0;
            *(float4*)&As[nb][ar0 + 64][ac] = t1;
            float4 u0 = make_float4(tf32_rna(pb0.x), tf32_rna(pb0.y), tf32_rna(pb0.z), tf32_rna(pb0.w));
            float4 u1 = make_float4(tf32_rna(pb1.x), tf32_rna(pb1.y), tf32_rna(pb1.z), tf32_rna(pb1.w));
            *(float4*)&Bs[nb][br0][bc]     = u0;
            *(float4*)&Bs[nb][br0 + 8][bc] = u1;
            __syncthreads();
            buf = nb;
        }
    }

    int colbase = bcol + n0;
    int s  = colbase / NC;
    int hd = colbase - s * NC;
    int h  = hd >> 6;

    #pragma unroll
    for (int mt = 0; mt < 4; ++mt) {
        #pragma unroll
        for (int half = 0; half < 2; ++half) {
            int m = brow + m0 + mt * 16 + gid + half * 8;
            if (m >= MROWS) continue;
            float* dst = nullptr;
            int d_off = 0;
            if (SCATTER) {
                int b  = m / NTOK;
                int n  = m - b * NTOK;
                int bh = b * NHEAD + h;
                if (s == 0) {
                    dst = &g_q[((size_t)bh * NTOK + n) * ND];
                } else {
                    int dest = g_dest[bh * NTOK + n];
                    if (dest >= 0)
                        dst = &((s == 1) ? g_kp : g_vp)[((size_t)bh * NKEEP + dest) * ND];
                }
                d_off = hd & 63;
            } else {
                dst = out + (size_t)m * LDW + colbase;
            }
            if (!dst) continue;
            #pragma unroll
            for (int nt = 0; nt < 4; ++nt) {
                int cl = nt * 8 + tid4 * 2;
                float2 bv = *(const float2*)(bias + colbase + cl);
                float2 o;
                o.x = c[mt][nt][half * 2 + 0] + bv.x;
                o.y = c[mt][nt][half * 2 + 1] + bv.y;
                *(float2*)(dst + (SCATTER ? d_off : 0) + cl) = o;
            }
        }
    }
}

// ---------------- attention: ONE CTA per (b,h); KV staged once -----------------
#define QS_STR 68
#define KS_STR 68
#define VS_STR 72
#define SS_STR 300
#define ATTN_SMEM ((32*QS_STR + NPAD*KS_STR + NPAD*VS_STR + 32*SS_STR) * 4)

__global__ __launch_bounds__(256) void attn_mma()
{
    extern __shared__ float sh[];
    float* Qs = sh;                        // 32 x 68
    float* Ks = Qs + 32 * QS_STR;          // 296 x 68
    float* Vs = Ks + NPAD * KS_STR;        // 296 x 72
    float* Ss = Vs + NPAD * VS_STR;        // 32 x 300

    int tid  = threadIdx.x;
    int bh   = blockIdx.x;
    int wid  = tid >> 5;
    int lane = tid & 31;
    int gid  = lane >> 2;
    int t4   = lane & 3;

    const float* kp = g_kp + (size_t)bh * NKEEP * ND;
    const float* vp = g_vp + (size_t)bh * NKEEP * ND;
    for (int idx = tid; idx < NPAD * ND; idx += 256) {
        int m = idx >> 6, d = idx & 63;
        float kv = 0.f, vv = 0.f;
        if (m < NKEEP) {
            kv = tf32_rna(kp[(size_t)m * ND + d]);
            vv = tf32_rna(vp[(size_t)m * ND + d]);
        }
        Ks[m * KS_STR + d] = kv;
        Vs[m * VS_STR + d] = vv;
    }
    const float* qp = g_q + (size_t)bh * NTOK * ND;
    int b = bh / NHEAD, h = bh - b * NHEAD;

    for (int q0 = 0; q0 < NTOK; q0 += 32) {
        for (int idx = tid; idx < 32 * ND; idx += 256) {
            int qq = idx >> 6, d = idx & 63;
            int qg = q0 + qq;
            Qs[qq * QS_STR + d] = (qg < NTOK) ? tf32_rna(qp[(size_t)qg * ND + d]) : 0.f;
        }
        __syncthreads();

        // Phase A: S = (Q K^T) * scale — ks-outer loop, Q frags hoisted,
        // register accumulators per nt (c[10][4]).
        {
            int wm = wid & 1, wn = wid >> 1;
            int m0 = wm * 16;
            float c[10][4];
            #pragma unroll
            for (int i = 0; i < 10; ++i) {
                c[i][0] = c[i][1] = c[i][2] = c[i][3] = 0.f;
            }
            #pragma unroll
            for (int ks = 0; ks < 8; ++ks) {
                int k0 = ks * 8;
                uint32_t a[4];
                a[0] = __float_as_uint(Qs[(m0 + gid) * QS_STR + k0 + t4]);
                a[1] = __float_as_uint(Qs[(m0 + gid + 8) * QS_STR + k0 + t4]);
                a[2] = __float_as_uint(Qs[(m0 + gid) * QS_STR + k0 + t4 + 4]);
                a[3] = __float_as_uint(Qs[(m0 + gid + 8) * QS_STR + k0 + t4 + 4]);
                #pragma unroll
                for (int i = 0; i < 10; ++i) {
                    int nt = wn + 4 * i;
                    if (nt >= NT8) break;
                    int nb = nt * 8;
                    uint32_t bb[2];
                    bb[0] = __float_as_uint(Ks[(nb + gid) * KS_STR + k0 + t4]);
                    bb[1] = __float_as_uint(Ks[(nb + gid) * KS_STR + k0 + t4 + 4]);
                    mma_tf32(c[i], a, bb);
                }
            }
            #pragma unroll
            for (int i = 0; i < 10; ++i) {
                int nt = wn + 4 * i;
                if (nt >= NT8) break;
                int nb = nt * 8;
                *(float2*)&Ss[(m0 + gid) * SS_STR + nb + 2 * t4]
                    = make_float2(c[i][0] * 0.125f, c[i][1] * 0.125f);
                *(float2*)&Ss[(m0 + gid + 8) * SS_STR + nb + 2 * t4]
                    = make_float2(c[i][2] * 0.125f, c[i][3] * 0.125f);
            }
        }
        __syncthreads();

        // Phase B: row softmax
        {
            int w = tid >> 5, ln = tid & 31;
            #pragma unroll
            for (int r = 0; r < 4; ++r) {
                float* Sr = Ss + (w * 4 + r) * SS_STR;
                float mx = -3.0e38f;
                for (int m = ln; m < NKEEP; m += 32) mx = fmaxf(mx, Sr[m]);
                #pragma unroll
                for (int o = 16; o; o >>= 1) mx = fmaxf(mx, __shfl_xor_sync(0xffffffffu, mx, o));
                float sum = 0.f;
                for (int m = ln; m < NKEEP; m += 32) {
                    float e = __expf(Sr[m] - mx);
                    Sr[m] = e;
                    sum += e;
                }
                #pragma unroll
                for (int o = 16; o; o >>= 1) sum += __shfl_xor_sync(0xffffffffu, sum, o);
                float inv = 1.f / sum;
                for (int m = ln; m < NKEEP; m += 32) Sr[m] *= inv;
            }
        }
        __syncthreads();

        // Phase C: O = P @ V
        {
            int wm = wid & 1, wn = wid >> 1;
            int m0 = wm * 16, n0 = wn * 16;
            float c[2][4];
            #pragma unroll
            for (int nt = 0; nt < 2; ++nt)
                #pragma unroll
                for (int r = 0; r < 4; ++r) c[nt][r] = 0.f;

            for (int ks = 0; ks < NT8; ++ks) {
                int k0 = ks * 8;
                uint32_t a[4];
                a[0] = __float_as_uint(tf32_rna(Ss[(m0 + gid) * SS_STR + k0 + t4]));
                a[1] = __float_as_uint(tf32_rna(Ss[(m0 + gid + 8) * SS_STR + k0 + t4]));
                a[2] = __float_as_uint(tf32_rna(Ss[(m0 + gid) * SS_STR + k0 + t4 + 4]));
                a[3] = __float_as_uint(tf32_rna(Ss[(m0 + gid + 8) * SS_STR + k0 + t4 + 4]));
                #pragma unroll
                for (int nt = 0; nt < 2; ++nt) {
                    uint32_t bb[2];
                    bb[0] = __float_as_uint(Vs[(k0 + t4) * VS_STR + n0 + nt * 8 + gid]);
                    bb[1] = __float_as_uint(Vs[(k0 + t4 + 4) * VS_STR + n0 + nt * 8 + gid]);
                    mma_tf32(c[nt], a, bb);
                }
            }

            #pragma unroll
            for (int half = 0; half < 2; ++half) {
                int qg = q0 + m0 + gid + half * 8;
                if (qg >= NTOK) continue;
                float* dst = &g_ao[((size_t)(b * NTOK + qg)) * NC + h * ND + n0];
                #pragma unroll
                for (int nt = 0; nt < 2; ++nt) {
                    float2 o;
                    o.x = c[nt][half * 2 + 0];
                    o.y = c[nt][half * 2 + 1];
                    *(float2*)(dst + nt * 8 + 2 * t4) = o;
                }
            }
        }
        __syncthreads();
    }
}

// ---------------- launch -------------------------------------------------------
extern "C" void kernel_launch(void* const* d_in, const int* in_sizes, int n_in,
                              void* d_out, int out_size)
{
    const float* x     = (const float*)d_in[0];
    const float* mask  = (const float*)d_in[1];
    const float* Wqkv  = (const float*)d_in[2];
    const float* bqkv  = (const float*)d_in[3];
    const float* Wproj = (const float*)d_in[4];
    const float* bproj = (const float*)d_in[5];
    float* out = (float*)d_out;

    select_kernel<<<NB * NHEAD, 256>>>(mask);

    dim3 g1(QCOLS / 128, (MROWS + 127) / 128);
    gemm_mma<QCOLS, true, false><<<g1, 256>>>(x, Wqkv, bqkv, nullptr);

    cudaFuncSetAttribute(attn_mma, cudaFuncAttributeMaxDynamicSharedMemorySize, ATTN_SMEM);
    attn_mma<<<NB * NHEAD, 256, ATTN_SMEM>>>();

    dim3 g2(NC / 128, (MROWS + 127) / 128);
    gemm_mma<NC, false, true><<<g2, 256>>>(nullptr, Wproj, bproj, out);
}

// round 10
// speedup vs baseline: 2.5345x; 1.2528x over previous
#include <cuda_runtime.h>
#include <cuda_fp16.h>
#include <cstdint>

#define NHEAD 12
#define NB    64
#define NTOK  577
#define NC    768
#define ND    64
#define NKEEP 289          // tokens kept incl. CLS
#define NMASK 576
#define MROWS (NB*NTOK)    // 36928
#define QCOLS (3*NC)       // 2304
#define NPAD  296          // padded kept-token count (37 x 8)
#define NT8   37           // n-tiles of 8 in padded token dim

// ---------------- scratch (static device globals; no allocations) -------------
__device__ __align__(16) float g_q [(size_t)NB*NHEAD*NTOK*ND];   // [B,H,N,D]
__device__ __align__(16) float g_kp[(size_t)NB*NHEAD*NKEEP*ND];  // gathered K
__device__ __align__(16) float g_vp[(size_t)NB*NHEAD*NKEEP*ND];  // gathered V
__device__ __align__(16) float g_ao[(size_t)NB*NTOK*NC];         // attn out [B,N,C]
__device__ int g_dest[NB*NHEAD*NTOK];                            // token -> kept slot (-1 = dropped)

// ---------------- helpers ------------------------------------------------------
__device__ __forceinline__ float tf32_rna(float v) {
    uint32_t u;
    asm("cvt.rna.tf32.f32 %0, %1;" : "=r"(u) : "f"(v));
    return __uint_as_float(u);
}
__device__ __forceinline__ void mma_tf32(float* c, const uint32_t* a, const uint32_t* b) {
    asm volatile(
        "mma.sync.aligned.m16n8k8.row.col.f32.tf32.tf32.f32 "
        "{%0,%1,%2,%3}, {%4,%5,%6,%7}, {%8,%9}, {%0,%1,%2,%3};\n"
        : "+f"(c[0]), "+f"(c[1]), "+f"(c[2]), "+f"(c[3])
        : "r"(a[0]), "r"(a[1]), "r"(a[2]), "r"(a[3]), "r"(b[0]), "r"(b[1]));
}
__device__ __forceinline__ void mma_f16(float* c, const uint32_t* a, const uint32_t* b) {
    asm volatile(
        "mma.sync.aligned.m16n8k16.row.col.f32.f16.f16.f32 "
        "{%0,%1,%2,%3}, {%4,%5,%6,%7}, {%8,%9}, {%0,%1,%2,%3};\n"
        : "+f"(c[0]), "+f"(c[1]), "+f"(c[2]), "+f"(c[3])
        : "r"(a[0]), "r"(a[1]), "r"(a[2]), "r"(a[3]), "r"(b[0]), "r"(b[1]));
}

// ---------------- token selection: exact top-288 of 576 per (b,h) -------------
__global__ __launch_bounds__(256) void select_kernel(const float* __restrict__ mask)
{
    int row = blockIdx.x;                       // b*NHEAD + h
    __shared__ float v[NMASK];
    __shared__ unsigned char keep[NMASK];
    const float* mrow = mask + (size_t)row * NMASK;
    for (int i = threadIdx.x; i < NMASK; i += 256) v[i] = mrow[i];
    __syncthreads();
    for (int i = threadIdx.x; i < NMASK; i += 256) {
        float vi = v[i];
        int cnt = 0;
        for (int j = 0; j < NMASK; ++j) {
            float vj = v[j];
            cnt += (vj > vi) || (vj == vi && j < i);   // top_k tie-break: lower index wins
        }
        keep[i] = (cnt < (NKEEP - 1)) ? 1 : 0;
    }
    __syncthreads();
    if (threadIdx.x == 0) {
        int* dm = g_dest + (size_t)row * NTOK;
        dm[0] = 0;
        int pos = 0;
        for (int i = 0; i < NMASK; ++i)
            dm[1 + i] = keep[i] ? (++pos) : -1;
    }
}

// ---------------- 128x128x16 fp16 mma.sync GEMM (f32 accum) --------------------
// As: [m][24] halfs (48B rows; frag half2 banks gid*12+t4 -> 32 distinct).
// Bs: half2 [kk][136] — .x/.y = consecutive k rows = exactly the B fragment.
#define AS_H 24
#define BS_H2 136
template<int LDW, bool SCATTER, bool USE_AO>
__global__ __launch_bounds__(256, 2) void gemm_mma(const float* __restrict__ Ain,
                                                   const float* __restrict__ W,
                                                   const float* __restrict__ bias,
                                                   float* __restrict__ out)
{
    const float* __restrict__ A = USE_AO ? (const float*)g_ao : Ain;
    __shared__ __half  As[2][128][AS_H];       // [stage][m][k(16)+pad]
    __shared__ __half2 Bs[2][8][BS_H2];        // [stage][kk][n(128)+pad]
    const int K = NC;

    int tid  = threadIdx.x;
    int brow = blockIdx.y * 128;
    int bcol = blockIdx.x * 128;

    // A loader: rows ar0, ar0+64; 4 k-floats each
    int ar0 = tid >> 2;
    int ac  = (tid & 3) << 2;
    // B loader: kk row pair, 4 n cols
    int bkk = tid >> 5;          // 0..7
    int bn  = (tid & 31) << 2;   // 0..124

    int wid  = tid >> 5;
    int lane = tid & 31;
    int gid  = lane >> 2;
    int tid4 = lane & 3;
    int m0 = (wid >> 2) * 64;
    int n0 = (wid & 3) * 32;

    bool aok0 = (brow + ar0)      < MROWS;
    bool aok1 = (brow + ar0 + 64) < MROWS;
    const float* Ap0 = A + (size_t)(brow + ar0) * K + ac;
    const float* Ap1 = Ap0 + (size_t)64 * K;
    const float* Wp0 = W + (size_t)(2 * bkk) * LDW + bcol + bn;
    const float* Wp1 = Wp0 + LDW;

    const float4 z4 = make_float4(0.f, 0.f, 0.f, 0.f);
    float4 pa0 = aok0 ? *(const float4*)Ap0 : z4;
    float4 pa1 = aok1 ? *(const float4*)Ap1 : z4;
    float4 pb0 = *(const float4*)Wp0;
    float4 pb1 = *(const float4*)Wp1;

    {
        __half2 q0 = __floats2half2_rn(pa0.x, pa0.y);
        __half2 q1 = __floats2half2_rn(pa0.z, pa0.w);
        *(uint2*)&As[0][ar0][ac] = make_uint2(*(uint32_t*)&q0, *(uint32_t*)&q1);
        __half2 q2 = __floats2half2_rn(pa1.x, pa1.y);
        __half2 q3 = __floats2half2_rn(pa1.z, pa1.w);
        *(uint2*)&As[0][ar0 + 64][ac] = make_uint2(*(uint32_t*)&q2, *(uint32_t*)&q3);
        __half2 r0 = __floats2half2_rn(pb0.x, pb1.x);
        __half2 r1 = __floats2half2_rn(pb0.y, pb1.y);
        __half2 r2 = __floats2half2_rn(pb0.z, pb1.z);
        __half2 r3 = __floats2half2_rn(pb0.w, pb1.w);
        *(uint4*)&Bs[0][bkk][bn] = make_uint4(*(uint32_t*)&r0, *(uint32_t*)&r1,
                                              *(uint32_t*)&r2, *(uint32_t*)&r3);
    }
    __syncthreads();

    float c[4][4][4];
    #pragma unroll
    for (int mt = 0; mt < 4; ++mt)
        #pragma unroll
        for (int nt = 0; nt < 4; ++nt)
            #pragma unroll
            for (int r = 0; r < 4; ++r) c[mt][nt][r] = 0.f;

    int buf = 0;
    for (int kt = 16; kt <= K; kt += 16) {
        bool more = kt < K;
        if (more) {
            pa0 = aok0 ? *(const float4*)(Ap0 + kt) : z4;
            pa1 = aok1 ? *(const float4*)(Ap1 + kt) : z4;
            pb0 = *(const float4*)(Wp0 + (size_t)kt * LDW);
            pb1 = *(const float4*)(Wp1 + (size_t)kt * LDW);
        }
        {
            uint32_t bf[4][2], af[4][4];
            #pragma unroll
            for (int nt = 0; nt < 4; ++nt) {
                bf[nt][0] = *(uint32_t*)&Bs[buf][tid4][n0 + nt*8 + gid];
                bf[nt][1] = *(uint32_t*)&Bs[buf][tid4 + 4][n0 + nt*8 + gid];
            }
            #pragma unroll
            for (int mt = 0; mt < 4; ++mt) {
                af[mt][0] = *(uint32_t*)&As[buf][m0 + mt*16 + gid][2*tid4];
                af[mt][1] = *(uint32_t*)&As[buf][m0 + mt*16 + gid + 8][2*tid4];
                af[mt][2] = *(uint32_t*)&As[buf][m0 + mt*16 + gid][2*tid4 + 8];
                af[mt][3] = *(uint32_t*)&As[buf][m0 + mt*16 + gid + 8][2*tid4 + 8];
            }
            #pragma unroll
            for (int mt = 0; mt < 4; ++mt)
                #pragma unroll
                for (int nt = 0; nt < 4; ++nt)
                    mma_f16(c[mt][nt], af[mt], bf[nt]);
        }
        if (more) {
            int nb = buf ^ 1;
            __half2 q0 = __floats2half2_rn(pa0.x, pa0.y);
            __half2 q1 = __floats2half2_rn(pa0.z, pa0.w);
            *(uint2*)&As[nb][ar0][ac] = make_uint2(*(uint32_t*)&q0, *(uint32_t*)&q1);
            __half2 q2 = __floats2half2_rn(pa1.x, pa1.y);
            __half2 q3 = __floats2half2_rn(pa1.z, pa1.w);
            *(uint2*)&As[nb][ar0 + 64][ac] = make_uint2(*(uint32_t*)&q2, *(uint32_t*)&q3);
            __half2 r0 = __floats2half2_rn(pb0.x, pb1.x);
            __half2 r1 = __floats2half2_rn(pb0.y, pb1.y);
            __half2 r2 = __floats2half2_rn(pb0.z, pb1.z);
            __half2 r3 = __floats2half2_rn(pb0.w, pb1.w);
            *(uint4*)&Bs[nb][bkk][bn] = make_uint4(*(uint32_t*)&r0, *(uint32_t*)&r1,
                                                   *(uint32_t*)&r2, *(uint32_t*)&r3);
            __syncthreads();
            buf = nb;
        }
    }

    int colbase = bcol + n0;
    int s  = colbase / NC;
    int hd = colbase - s * NC;
    int h  = hd >> 6;

    #pragma unroll
    for (int mt = 0; mt < 4; ++mt) {
        #pragma unroll
        for (int half = 0; half < 2; ++half) {
            int m = brow + m0 + mt * 16 + gid + half * 8;
            if (m >= MROWS) continue;
            float* dst = nullptr;
            int d_off = 0;
            if (SCATTER) {
                int b  = m / NTOK;
                int n  = m - b * NTOK;
                int bh = b * NHEAD + h;
                if (s == 0) {
                    dst = &g_q[((size_t)bh * NTOK + n) * ND];
                } else {
                    int dest = g_dest[bh * NTOK + n];
                    if (dest >= 0)
                        dst = &((s == 1) ? g_kp : g_vp)[((size_t)bh * NKEEP + dest) * ND];
                }
                d_off = hd & 63;
            } else {
                dst = out + (size_t)m * LDW + colbase;
            }
            if (!dst) continue;
            #pragma unroll
            for (int nt = 0; nt < 4; ++nt) {
                int cl = nt * 8 + tid4 * 2;
                float2 bv = *(const float2*)(bias + colbase + cl);
                float2 o;
                o.x = c[mt][nt][half * 2 + 0] + bv.x;
                o.y = c[mt][nt][half * 2 + 1] + bv.y;
                *(float2*)(dst + (SCATTER ? d_off : 0) + cl) = o;
            }
        }
    }
}

// ---------------- attention: ONE CTA per (b,h); KV staged once (R9) ------------
#define QS_STR 68
#define KS_STR 68
#define VS_STR 72
#define SS_STR 300
#define ATTN_SMEM ((32*QS_STR + NPAD*KS_STR + NPAD*VS_STR + 32*SS_STR) * 4)

__global__ __launch_bounds__(256) void attn_mma()
{
    extern __shared__ float sh[];
    float* Qs = sh;                        // 32 x 68
    float* Ks = Qs + 32 * QS_STR;          // 296 x 68
    float* Vs = Ks + NPAD * KS_STR;        // 296 x 72
    float* Ss = Vs + NPAD * VS_STR;        // 32 x 300

    int tid  = threadIdx.x;
    int bh   = blockIdx.x;
    int wid  = tid >> 5;
    int lane = tid & 31;
    int gid  = lane >> 2;
    int t4   = lane & 3;

    const float* kp = g_kp + (size_t)bh * NKEEP * ND;
    const float* vp = g_vp + (size_t)bh * NKEEP * ND;
    for (int idx = tid; idx < NPAD * ND; idx += 256) {
        int m = idx >> 6, d = idx & 63;
        float kv = 0.f, vv = 0.f;
        if (m < NKEEP) {
            kv = tf32_rna(kp[(size_t)m * ND + d]);
            vv = tf32_rna(vp[(size_t)m * ND + d]);
        }
        Ks[m * KS_STR + d] = kv;
        Vs[m * VS_STR + d] = vv;
    }
    const float* qp = g_q + (size_t)bh * NTOK * ND;
    int b = bh / NHEAD, h = bh - b * NHEAD;

    for (int q0 = 0; q0 < NTOK; q0 += 32) {
        for (int idx = tid; idx < 32 * ND; idx += 256) {
            int qq = idx >> 6, d = idx & 63;
            int qg = q0 + qq;
            Qs[qq * QS_STR + d] = (qg < NTOK) ? tf32_rna(qp[(size_t)qg * ND + d]) : 0.f;
        }
        __syncthreads();

        // Phase A: S = (Q K^T) * scale — ks-outer, Q frags hoisted
        {
            int wm = wid & 1, wn = wid >> 1;
            int m0 = wm * 16;
            float c[10][4];
            #pragma unroll
            for (int i = 0; i < 10; ++i) {
                c[i][0] = c[i][1] = c[i][2] = c[i][3] = 0.f;
            }
            #pragma unroll
            for (int ks = 0; ks < 8; ++ks) {
                int k0 = ks * 8;
                uint32_t a[4];
                a[0] = __float_as_uint(Qs[(m0 + gid) * QS_STR + k0 + t4]);
                a[1] = __float_as_uint(Qs[(m0 + gid + 8) * QS_STR + k0 + t4]);
                a[2] = __float_as_uint(Qs[(m0 + gid) * QS_STR + k0 + t4 + 4]);
                a[3] = __float_as_uint(Qs[(m0 + gid + 8) * QS_STR + k0 + t4 + 4]);
                #pragma unroll
                for (int i = 0; i < 10; ++i) {
                    int nt = wn + 4 * i;
                    if (nt >= NT8) break;
                    int nb = nt * 8;
                    uint32_t bb[2];
                    bb[0] = __float_as_uint(Ks[(nb + gid) * KS_STR + k0 + t4]);
                    bb[1] = __float_as_uint(Ks[(nb + gid) * KS_STR + k0 + t4 + 4]);
                    mma_tf32(c[i], a, bb);
                }
            }
            #pragma unroll
            for (int i = 0; i < 10; ++i) {
                int nt = wn + 4 * i;
                if (nt >= NT8) break;
                int nb = nt * 8;
                *(float2*)&Ss[(m0 + gid) * SS_STR + nb + 2 * t4]
                    = make_float2(c[i][0] * 0.125f, c[i][1] * 0.125f);
                *(float2*)&Ss[(m0 + gid + 8) * SS_STR + nb + 2 * t4]
                    = make_float2(c[i][2] * 0.125f, c[i][3] * 0.125f);
            }
        }
        __syncthreads();

        // Phase B: row softmax
        {
            int w = tid >> 5, ln = tid & 31;
            #pragma unroll
            for (int r = 0; r < 4; ++r) {
                float* Sr = Ss + (w * 4 + r) * SS_STR;
                float mx = -3.0e38f;
                for (int m = ln; m < NKEEP; m += 32) mx = fmaxf(mx, Sr[m]);
                #pragma unroll
                for (int o = 16; o; o >>= 1) mx = fmaxf(mx, __shfl_xor_sync(0xffffffffu, mx, o));
                float sum = 0.f;
                for (int m = ln; m < NKEEP; m += 32) {
                    float e = __expf(Sr[m] - mx);
                    Sr[m] = e;
                    sum += e;
                }
                #pragma unroll
                for (int o = 16; o; o >>= 1) sum += __shfl_xor_sync(0xffffffffu, sum, o);
                float inv = 1.f / sum;
                for (int m = ln; m < NKEEP; m += 32) Sr[m] *= inv;
            }
        }
        __syncthreads();

        // Phase C: O = P @ V
        {
            int wm = wid & 1, wn = wid >> 1;
            int m0 = wm * 16, n0 = wn * 16;
            float c[2][4];
            #pragma unroll
            for (int nt = 0; nt < 2; ++nt)
                #pragma unroll
                for (int r = 0; r < 4; ++r) c[nt][r] = 0.f;

            for (int ks = 0; ks < NT8; ++ks) {
                int k0 = ks * 8;
                uint32_t a[4];
                a[0] = __float_as_uint(tf32_rna(Ss[(m0 + gid) * SS_STR + k0 + t4]));
                a[1] = __float_as_uint(tf32_rna(Ss[(m0 + gid + 8) * SS_STR + k0 + t4]));
                a[2] = __float_as_uint(tf32_rna(Ss[(m0 + gid) * SS_STR + k0 + t4 + 4]));
                a[3] = __float_as_uint(tf32_rna(Ss[(m0 + gid + 8) * SS_STR + k0 + t4 + 4]));
                #pragma unroll
                for (int nt = 0; nt < 2; ++nt) {
                    uint32_t bb[2];
                    bb[0] = __float_as_uint(Vs[(k0 + t4) * VS_STR + n0 + nt * 8 + gid]);
                    bb[1] = __float_as_uint(Vs[(k0 + t4 + 4) * VS_STR + n0 + nt * 8 + gid]);
                    mma_tf32(c[nt], a, bb);
                }
            }

            #pragma unroll
            for (int half = 0; half < 2; ++half) {
                int qg = q0 + m0 + gid + half * 8;
                if (qg >= NTOK) continue;
                float* dst = &g_ao[((size_t)(b * NTOK + qg)) * NC + h * ND + n0];
                #pragma unroll
                for (int nt = 0; nt < 2; ++nt) {
                    float2 o;
                    o.x = c[nt][half * 2 + 0];
                    o.y = c[nt][half * 2 + 1];
                    *(float2*)(dst + nt * 8 + 2 * t4) = o;
                }
            }
        }
        __syncthreads();
    }
}

// ---------------- launch -------------------------------------------------------
extern "C" void kernel_launch(void* const* d_in, const int* in_sizes, int n_in,
                              void* d_out, int out_size)
{
    const float* x     = (const float*)d_in[0];
    const float* mask  = (const float*)d_in[1];
    const float* Wqkv  = (const float*)d_in[2];
    const float* bqkv  = (const float*)d_in[3];
    const float* Wproj = (const float*)d_in[4];
    const float* bproj = (const float*)d_in[5];
    float* out = (float*)d_out;

    select_kernel<<<NB * NHEAD, 256>>>(mask);

    dim3 g1(QCOLS / 128, (MROWS + 127) / 128);
    gemm_mma<QCOLS, true, false><<<g1, 256>>>(x, Wqkv, bqkv, nullptr);

    cudaFuncSetAttribute(attn_mma, cudaFuncAttributeMaxDynamicSharedMemorySize, ATTN_SMEM);
    attn_mma<<<NB * NHEAD, 256, ATTN_SMEM>>>();

    dim3 g2(NC / 128, (MROWS + 127) / 128);
    gemm_mma<NC, false, true><<<g2, 256>>>(nullptr, Wproj, bproj, out);
}